// round 14
// baseline (speedup 1.0000x reference)
#include <cuda_runtime.h>
#include <cuda_fp16.h>
#include <cstdint>

#define SEQL 4096
#define DMODEL 1024
#define NH 16
#define DKH 64

// Scratch (allocation-free rule: static device globals) — all fp16 hi/lo
static __device__ __half g_Qih[SEQL * DMODEL], g_Qil[SEQL * DMODEL];
static __device__ __half g_Kih[SEQL * DMODEL], g_Kil[SEQL * DMODEL];
static __device__ __half g_Vih[SEQL * DMODEL], g_Vil[SEQL * DMODEL];
static __device__ __half g_Wqh[DMODEL * DMODEL], g_Wql[DMODEL * DMODEL];
static __device__ __half g_Wkh[DMODEL * DMODEL], g_Wkl[DMODEL * DMODEL];
static __device__ __half g_Wvh[DMODEL * DMODEL], g_Wvl[DMODEL * DMODEL];
static __device__ __half g_Woh[DMODEL * DMODEL], g_Wol[DMODEL * DMODEL];
static __device__ __half g_Qhh[SEQL * DMODEL], g_Qhl[SEQL * DMODEL];
static __device__ __half g_Khh[SEQL * DMODEL], g_Khl[SEQL * DMODEL];
static __device__ __half g_Vhh[SEQL * DMODEL], g_Vhl[SEQL * DMODEL];
static __device__ __half g_Ohh[SEQL * DMODEL], g_Ohl[SEQL * DMODEL];

// ---------------- low-level helpers (base PTX only, no 'a' features) -------
__device__ __forceinline__ uint32_t smem_u32(const void* p) {
    uint32_t a;
    asm("{ .reg .u64 t; cvta.to.shared.u64 t, %1; cvt.u32.u64 %0, t; }" : "=r"(a) : "l"(p));
    return a;
}
__device__ __forceinline__ void cp16(uint32_t dst, const void* src) {
    asm volatile("cp.async.cg.shared.global [%0], [%1], 16;" :: "r"(dst), "l"(src));
}
__device__ __forceinline__ void cp_commit() {
    asm volatile("cp.async.commit_group;" ::: "memory");
}
__device__ __forceinline__ void ldmx4(uint32_t* r, uint32_t addr) {
    asm volatile("ldmatrix.sync.aligned.m8n8.x4.shared.b16 {%0,%1,%2,%3}, [%4];"
                 : "=r"(r[0]), "=r"(r[1]), "=r"(r[2]), "=r"(r[3]) : "r"(addr));
}
__device__ __forceinline__ void ldmx4t(uint32_t* r, uint32_t addr) {
    asm volatile("ldmatrix.sync.aligned.m8n8.x4.trans.shared.b16 {%0,%1,%2,%3}, [%4];"
                 : "=r"(r[0]), "=r"(r[1]), "=r"(r[2]), "=r"(r[3]) : "r"(addr));
}
// fp16 inputs, fp32 accumulate
__device__ __forceinline__ void mma16816(float* c, const uint32_t* a, const uint32_t* b) {
    asm volatile(
        "mma.sync.aligned.m16n8k16.row.col.f32.f16.f16.f32 "
        "{%0,%1,%2,%3}, {%4,%5,%6,%7}, {%8,%9}, {%0,%1,%2,%3};"
        : "+f"(c[0]), "+f"(c[1]), "+f"(c[2]), "+f"(c[3])
        : "r"(a[0]), "r"(a[1]), "r"(a[2]), "r"(a[3]), "r"(b[0]), "r"(b[1]));
}
// fp32 pair -> fp16 hi frag + fp16 residual frag
__device__ __forceinline__ void pconv(float s0, float s1, uint32_t& ph, uint32_t& pl) {
    __half2 h2 = __floats2half2_rn(s0, s1);
    __half2 l2 = __floats2half2_rn(s0 - __half2float(__low2half(h2)),
                                   s1 - __half2float(__high2half(h2)));
    ph = *(uint32_t*)&h2;
    pl = *(uint32_t*)&l2;
}
// fp32 pair -> single fp16x2 frag
__device__ __forceinline__ uint32_t packh2(float s0, float s1) {
    __half2 h2 = __floats2half2_rn(s0, s1);
    return *(uint32_t*)&h2;
}

// Dummy launch so ncu (-s 5) lands on the flash kernel at launch index 5.
__global__ void idle_kernel() {}

// ---------------------------------------------------------------------------
// Merged split kernel. z<3: inputs Q/K/V (4 floats/thread).
// z in 3..6: weights WQ/WK/WV/WO -> Bt[n][k] (1 element/thread).
// ---------------------------------------------------------------------------
__global__ void split_all_kernel(
    const float* __restrict__ Q, const float* __restrict__ K,
    const float* __restrict__ V,
    const float* __restrict__ WQ, const float* __restrict__ WK,
    const float* __restrict__ WV, const float* __restrict__ WO,
    __half* __restrict__ Qih, __half* __restrict__ Qil,
    __half* __restrict__ Kih, __half* __restrict__ Kil,
    __half* __restrict__ Vih, __half* __restrict__ Vil,
    __half* __restrict__ Wqh, __half* __restrict__ Wql,
    __half* __restrict__ Wkh, __half* __restrict__ Wkl,
    __half* __restrict__ Wvh, __half* __restrict__ Wvl,
    __half* __restrict__ Woh, __half* __restrict__ Wol)
{
    const int z = blockIdx.z;
    if (z < 3) {
        const float* X = (z == 0) ? Q : (z == 1) ? K : V;
        __half* H = (z == 0) ? Qih : (z == 1) ? Kih : Vih;
        __half* L = (z == 0) ? Qil : (z == 1) ? Kil : Vil;
        int i = (blockIdx.x * blockDim.x + threadIdx.x) * 4;
        float4 v = *(const float4*)(X + i);
        float vv[4] = {v.x, v.y, v.z, v.w};
        __half h[4], l[4];
#pragma unroll
        for (int j = 0; j < 4; j++) {
            h[j] = __float2half_rn(vv[j]);
            l[j] = __float2half_rn(vv[j] - __half2float(h[j]));
        }
        *(__half2*)(H + i)     = __half2(h[0], h[1]);
        *(__half2*)(H + i + 2) = __half2(h[2], h[3]);
        *(__half2*)(L + i)     = __half2(l[0], l[1]);
        *(__half2*)(L + i + 2) = __half2(l[2], l[3]);
    } else {
        const int w = z - 3;
        const float* W = (w == 0) ? WQ : (w == 1) ? WK : (w == 2) ? WV : WO;
        __half* H = (w == 0) ? Wqh : (w == 1) ? Wkh : (w == 2) ? Wvh : Woh;
        __half* L = (w == 0) ? Wql : (w == 1) ? Wkl : (w == 2) ? Wvl : Wol;
        int idx = blockIdx.x * blockDim.x + threadIdx.x;   // = n*1024 + k
        int n = idx >> 10, k = idx & 1023;
        float v = (w < 3) ? W[(n >> 6) * (DMODEL * DKH) + k * DKH + (n & 63)]
                          : W[k * DMODEL + n];
        __half h = __float2half_rn(v);
        H[idx] = h;
        L[idx] = __float2half_rn(v - __half2float(h));
    }
}

// ---------------------------------------------------------------------------
// fp16 GEMM on mma.sync:  C = A @ Bt^T.  (unchanged from R13)
// terms==3: AhBh + AhBl + AlBh; terms==2: AhBh + AlBh.
// CTA tile M=128 x N=256, BK=32, 512 threads, 3-stage cp.async pipeline.
// ---------------------------------------------------------------------------
#define OA_H 0
#define OA_L 10240
#define OB_H 20480
#define OB_L 40960
#define GSTG 61440
#define GSMEM (3 * GSTG)

__global__ __launch_bounds__(512, 1) void tc_gemm_kernel(
    const __half* __restrict__ Ah, const __half* __restrict__ Al,
    const __half* __restrict__ Bh, const __half* __restrict__ Bl,
    float* __restrict__ Cf,
    __half* __restrict__ Ch, __half* __restrict__ Cl, int terms)
{
    extern __shared__ char smem[];
    const uint32_t sb = smem_u32(smem);
    const int tid = threadIdx.x;
    const int wid = tid >> 5, lane = tid & 31;
    const int m0 = blockIdx.y * 128;
    const int n0 = blockIdx.x * 256;
    const int wm0 = (wid & 1) * 64;
    const int wn0 = (wid >> 1) * 32;

    float acc[4][4][4];
#pragma unroll
    for (int i = 0; i < 4; i++)
#pragma unroll
        for (int j = 0; j < 4; j++)
#pragma unroll
            for (int t = 0; t < 4; t++) acc[i][j][t] = 0.f;

    const int ar = tid >> 2, ac = tid & 3;
    const int br = tid >> 1, bc = (2 * tid) & 3;

    auto load_stage = [&](int st, int k0) {
        uint32_t base = sb + st * GSTG;
        const __half* ga  = Ah + (m0 + ar) * DMODEL + k0 + ac * 8;
        const __half* gal = Al + (m0 + ar) * DMODEL + k0 + ac * 8;
        const __half* gb  = Bh + (n0 + br) * DMODEL + k0 + bc * 8;
        uint32_t soA = ar * 80 + ac * 16;
        uint32_t soB = br * 80 + bc * 16;
        cp16(base + OA_H + soA, ga);
        cp16(base + OA_L + soA, gal);
        cp16(base + OB_H + soB, gb);   cp16(base + OB_H + soB + 16, gb + 8);
        if (terms == 3) {
            const __half* gbl = Bl + (n0 + br) * DMODEL + k0 + bc * 8;
            cp16(base + OB_L + soB, gbl);  cp16(base + OB_L + soB + 16, gbl + 8);
        }
    };

    load_stage(0, 0);
    cp_commit();
    load_stage(1, 32);
    cp_commit();

    for (int kc = 0; kc < 32; kc++) {
        asm volatile("cp.async.wait_group 1;" ::: "memory");
        __syncthreads();
        if (kc + 2 < 32) load_stage((kc + 2) % 3, (kc + 2) * 32);
        cp_commit();

        uint32_t base = sb + (kc % 3) * GSTG;
#pragma unroll
        for (int k16 = 0; k16 < 32; k16 += 16) {
            uint32_t bh[4][2], bl[4][2];
#pragma unroll
            for (int bt = 0; bt < 2; bt++) {
                int nrow = wn0 + bt * 16 + (lane & 7) + ((lane >> 4) << 3);
                int kcol = k16 + ((lane >> 3) & 1) * 8;
                uint32_t ad = base + OB_H + nrow * 80 + kcol * 2;
                uint32_t r[4];
                ldmx4(r, ad);
                bh[bt * 2][0] = r[0]; bh[bt * 2][1] = r[1];
                bh[bt * 2 + 1][0] = r[2]; bh[bt * 2 + 1][1] = r[3];
                if (terms == 3) {
                    ldmx4(r, ad + (OB_L - OB_H));
                    bl[bt * 2][0] = r[0]; bl[bt * 2][1] = r[1];
                    bl[bt * 2 + 1][0] = r[2]; bl[bt * 2 + 1][1] = r[3];
                }
            }
#pragma unroll
            for (int mt = 0; mt < 4; mt++) {
                int mrow = wm0 + mt * 16 + (lane & 15);
                int kcol = k16 + (lane >> 4) * 8;
                uint32_t ad = base + OA_H + mrow * 80 + kcol * 2;
                uint32_t ah[4], al[4];
                ldmx4(ah, ad);
                ldmx4(al, ad + (OA_L - OA_H));
#pragma unroll
                for (int nt = 0; nt < 4; nt++) mma16816(acc[mt][nt], ah, bh[nt]);
#pragma unroll
                for (int nt = 0; nt < 4; nt++) mma16816(acc[mt][nt], al, bh[nt]);
                if (terms == 3) {
#pragma unroll
                    for (int nt = 0; nt < 4; nt++) mma16816(acc[mt][nt], ah, bl[nt]);
                }
            }
        }
    }

    const int er = lane >> 2;
    const int ec = 2 * (lane & 3);
    if (Ch == nullptr) {
#pragma unroll
        for (int mt = 0; mt < 4; mt++)
#pragma unroll
            for (int nt = 0; nt < 4; nt++) {
                int r = m0 + wm0 + mt * 16 + er;
                int c = n0 + wn0 + nt * 8 + ec;
                *(float2*)(Cf + r * DMODEL + c) = make_float2(acc[mt][nt][0], acc[mt][nt][1]);
                *(float2*)(Cf + (r + 8) * DMODEL + c) = make_float2(acc[mt][nt][2], acc[mt][nt][3]);
            }
    } else {
#pragma unroll
        for (int mt = 0; mt < 4; mt++)
#pragma unroll
            for (int nt = 0; nt < 4; nt++) {
                int r = m0 + wm0 + mt * 16 + er;
                int c = n0 + wn0 + nt * 8 + ec;
                uint32_t h0, l0, h1, l1;
                pconv(acc[mt][nt][0], acc[mt][nt][1], h0, l0);
                pconv(acc[mt][nt][2], acc[mt][nt][3], h1, l1);
                *(uint32_t*)(Ch + r * DMODEL + c) = h0;
                *(uint32_t*)(Cl + r * DMODEL + c) = l0;
                *(uint32_t*)(Ch + (r + 8) * DMODEL + c) = h1;
                *(uint32_t*)(Cl + (r + 8) * DMODEL + c) = l1;
            }
    }
}

// ---------------------------------------------------------------------------
// Flash attention on mma.sync, causal. fp16 numerics (unchanged):
//   S = Qh Kh^T + Qh Kl^T + Ql Kh^T ; O += P V (single fp16)
// NEW GEOMETRY: CTA = 256 q-rows x 1 head, 512 threads / 16 warps
// (4 warps/SMSP for latency hiding; KV smem traffic halves).
// Interleaved K/V fragment loads keep regs <= 128. 3-stage KV pipeline.
// Smem: Qh@0 (32KB), Ql@32768 (32KB), stage s @ 65536 + s*24576
//   (Kh@0, Kl@8192, Vh@16384 within stage). Total 136KB.
// ---------------------------------------------------------------------------
#define FSTG 24576
#define FSMEM (65536 + 3 * FSTG)

__global__ __launch_bounds__(512, 1) void flash_mma_kernel(
    const __half* __restrict__ Qh, const __half* __restrict__ Ql,
    const __half* __restrict__ Kh, const __half* __restrict__ Kl,
    const __half* __restrict__ Vh,
    __half* __restrict__ Oh, __half* __restrict__ Ol)
{
    extern __shared__ char fsm[];
    const uint32_t sb = smem_u32(fsm);
    const int tid = threadIdx.x;
    const int lane = tid & 31, wid = tid >> 5;      // wid 0..15
    const int h = blockIdx.y;
    const int qt = gridDim.x - 1 - (int)blockIdx.x;  // long tiles first
    const int q0 = qt * 256;
    const int cb = h * DKH;
    const int nk = 4 * (qt + 1);
    const int wq = wid * 16;
    const int lr8 = lane & 7, lg = lane >> 3;

    auto load_kv = [&](int stage, int s0) {
        uint32_t base = sb + 65536 + stage * FSTG;
        int r = tid >> 3, u = tid & 7;               // 512 = 64 rows x 8 units
        uint32_t so = r * 128 + ((u ^ (r & 7)) << 4);
        int go = (s0 + r) * DMODEL + cb + u * 8;
        cp16(base + so, Kh + go);
        cp16(base + 8192 + so, Kl + go);
        cp16(base + 16384 + so, Vh + go);
    };

    // group 0: Q(h,l) + KV stage 0
#pragma unroll
    for (int i = 0; i < 4; i++) {
        int idx = i * 512 + tid;                     // 2048 = 256 rows x 8 units
        int r = idx >> 3, u = idx & 7;
        uint32_t so = r * 128 + ((u ^ (r & 7)) << 4);
        int go = (q0 + r) * DMODEL + cb + u * 8;
        cp16(sb + so, Qh + go);
        cp16(sb + 32768 + so, Ql + go);
    }
    load_kv(0, 0);
    cp_commit();
    load_kv(1, 64);        // nk >= 4 always
    cp_commit();

    float m_lo = -1e30f, m_hi = -1e30f, l_lo = 0.f, l_hi = 0.f;
    float oacc[8][4];
#pragma unroll
    for (int t = 0; t < 8; t++)
#pragma unroll
        for (int e = 0; e < 4; e++) oacc[t][e] = 0.f;
    uint32_t qha[4][4], qla[4][4];

    for (int kt = 0; kt < nk; kt++) {
        asm volatile("cp.async.wait_group 1;" ::: "memory");
        __syncthreads();
        if (kt + 2 < nk) load_kv((kt + 2) % 3, (kt + 2) * 64);
        cp_commit();

        if (kt == 0) {
#pragma unroll
            for (int ks = 0; ks < 4; ks++) {
                int qr = wq + (lg & 1) * 8 + lr8;
                int u = 2 * ks + (lg >> 1);
                uint32_t a = sb + qr * 128 + ((u ^ (qr & 7)) << 4);
                ldmx4(qha[ks], a);
                ldmx4(qla[ks], a + 32768);
            }
        }

        const uint32_t kvb = sb + 65536 + (kt % 3) * FSTG;
        const bool skip = (kt * 64 > q0 + wq + 15);
        if (!skip) {
            // ---- S = Q K^T (3-term fp16, interleaved frag loads, low regs)
            float sacc[8][4];
#pragma unroll
            for (int t = 0; t < 8; t++)
#pragma unroll
                for (int e = 0; e < 4; e++) sacc[t][e] = 0.f;

#pragma unroll
            for (int ks = 0; ks < 4; ks++) {
#pragma unroll
                for (int pj = 0; pj < 4; pj++) {
                    int kr = pj * 16 + (lg >> 1) * 8 + lr8;
                    int u = 2 * ks + (lg & 1);
                    uint32_t ka = kvb + kr * 128 + ((u ^ (kr & 7)) << 4);
                    uint32_t kh[4], kl[4];
                    ldmx4(kh, ka);
                    ldmx4(kl, ka + 8192);
                    mma16816(sacc[2 * pj], qha[ks], kh);
                    mma16816(sacc[2 * pj], qha[ks], kl);
                    mma16816(sacc[2 * pj], qla[ks], kh);
                    mma16816(sacc[2 * pj + 1], qha[ks], kh + 2);
                    mma16816(sacc[2 * pj + 1], qha[ks], kl + 2);
                    mma16816(sacc[2 * pj + 1], qla[ks], kh + 2);
                }
            }

            // ---- scale + causal mask
            const int gr_lo = q0 + wq + (lane >> 2);
            const bool maskt = (kt * 64 + 63 > q0 + wq);
#pragma unroll
            for (int t = 0; t < 8; t++)
#pragma unroll
                for (int e = 0; e < 4; e++) {
                    float s = sacc[t][e] * 0.125f;
                    if (maskt) {
                        int col = kt * 64 + t * 8 + 2 * (lane & 3) + (e & 1);
                        int row = gr_lo + ((e >> 1) << 3);
                        if (col > row) s = -1e9f;
                    }
                    sacc[t][e] = s;
                }

            // ---- online softmax
            float rx_lo = -1e30f, rx_hi = -1e30f;
#pragma unroll
            for (int t = 0; t < 8; t++) {
                rx_lo = fmaxf(rx_lo, fmaxf(sacc[t][0], sacc[t][1]));
                rx_hi = fmaxf(rx_hi, fmaxf(sacc[t][2], sacc[t][3]));
            }
            rx_lo = fmaxf(rx_lo, __shfl_xor_sync(0xffffffffu, rx_lo, 1));
            rx_lo = fmaxf(rx_lo, __shfl_xor_sync(0xffffffffu, rx_lo, 2));
            rx_hi = fmaxf(rx_hi, __shfl_xor_sync(0xffffffffu, rx_hi, 1));
            rx_hi = fmaxf(rx_hi, __shfl_xor_sync(0xffffffffu, rx_hi, 2));

            float mn_lo = fmaxf(m_lo, rx_lo);
            float mn_hi = fmaxf(m_hi, rx_hi);
            float al_lo = __expf(m_lo - mn_lo);
            float al_hi = __expf(m_hi - mn_hi);
            m_lo = mn_lo; m_hi = mn_hi;

            float sm_lo = 0.f, sm_hi = 0.f;
#pragma unroll
            for (int t = 0; t < 8; t++) {
                sacc[t][0] = __expf(sacc[t][0] - m_lo);
                sacc[t][1] = __expf(sacc[t][1] - m_lo);
                sacc[t][2] = __expf(sacc[t][2] - m_hi);
                sacc[t][3] = __expf(sacc[t][3] - m_hi);
                sm_lo += sacc[t][0] + sacc[t][1];
                sm_hi += sacc[t][2] + sacc[t][3];
            }
            sm_lo += __shfl_xor_sync(0xffffffffu, sm_lo, 1);
            sm_lo += __shfl_xor_sync(0xffffffffu, sm_lo, 2);
            sm_hi += __shfl_xor_sync(0xffffffffu, sm_hi, 1);
            sm_hi += __shfl_xor_sync(0xffffffffu, sm_hi, 2);
            l_lo = l_lo * al_lo + sm_lo;
            l_hi = l_hi * al_hi + sm_hi;
#pragma unroll
            for (int t = 0; t < 8; t++) {
                oacc[t][0] *= al_lo; oacc[t][1] *= al_lo;
                oacc[t][2] *= al_hi; oacc[t][3] *= al_hi;
            }

            // ---- O += P V (single-term fp16, interleaved V loads)
#pragma unroll
            for (int ks = 0; ks < 4; ks++) {
                uint32_t ph[4];
                int t0 = 2 * ks, t1 = 2 * ks + 1;
                ph[0] = packh2(sacc[t0][0], sacc[t0][1]);
                ph[1] = packh2(sacc[t0][2], sacc[t0][3]);
                ph[2] = packh2(sacc[t1][0], sacc[t1][1]);
                ph[3] = packh2(sacc[t1][2], sacc[t1][3]);
#pragma unroll
                for (int pj = 0; pj < 4; pj++) {
                    int vr = ks * 16 + (lg & 1) * 8 + lr8;
                    int u = 2 * pj + (lg >> 1);
                    uint32_t va = kvb + 16384 + vr * 128 + ((u ^ (vr & 7)) << 4);
                    uint32_t vh[4];
                    ldmx4t(vh, va);
                    mma16816(oacc[2 * pj], ph, vh);
                    mma16816(oacc[2 * pj + 1], ph, vh + 2);
                }
            }
        }
    }

    // ---- epilogue: normalize, fp16 hi/lo split, store
    const float inv_lo = 1.0f / l_lo;
    const float inv_hi = 1.0f / l_hi;
    const int gr_lo = q0 + wq + (lane >> 2);
#pragma unroll
    for (int t = 0; t < 8; t++) {
        int c = cb + t * 8 + 2 * (lane & 3);
        {
            float o0 = oacc[t][0] * inv_lo, o1 = oacc[t][1] * inv_lo;
            uint32_t hh, ll;
            pconv(o0, o1, hh, ll);
            *(uint32_t*)(Oh + gr_lo * DMODEL + c) = hh;
            *(uint32_t*)(Ol + gr_lo * DMODEL + c) = ll;
        }
        {
            float o0 = oacc[t][2] * inv_hi, o1 = oacc[t][3] * inv_hi;
            uint32_t hh, ll;
            pconv(o0, o1, hh, ll);
            *(uint32_t*)(Oh + (gr_lo + 8) * DMODEL + c) = hh;
            *(uint32_t*)(Ol + (gr_lo + 8) * DMODEL + c) = ll;
        }
    }
}

// ---------------------------------------------------------------------------
extern "C" void kernel_launch(void* const* d_in, const int* in_sizes, int n_in,
                              void* d_out, int out_size)
{
    const float* Q  = (const float*)d_in[0];
    const float* K  = (const float*)d_in[1];
    const float* V  = (const float*)d_in[2];
    const float* WQ = (const float*)d_in[3];
    const float* WK = (const float*)d_in[4];
    const float* WV = (const float*)d_in[5];
    const float* WO = (const float*)d_in[6];
    float* out = (float*)d_out;

    __half *qih, *qil, *kih, *kil, *vih, *vil;
    __half *wqh, *wql, *wkh, *wkl, *wvh, *wvl, *woh, *wol;
    __half *qhh, *qhl, *khh, *khl, *vhh, *vhl, *ohh, *ohl;
    cudaGetSymbolAddress((void**)&qih, g_Qih); cudaGetSymbolAddress((void**)&qil, g_Qil);
    cudaGetSymbolAddress((void**)&kih, g_Kih); cudaGetSymbolAddress((void**)&kil, g_Kil);
    cudaGetSymbolAddress((void**)&vih, g_Vih); cudaGetSymbolAddress((void**)&vil, g_Vil);
    cudaGetSymbolAddress((void**)&wqh, g_Wqh); cudaGetSymbolAddress((void**)&wql, g_Wql);
    cudaGetSymbolAddress((void**)&wkh, g_Wkh); cudaGetSymbolAddress((void**)&wkl, g_Wkl);
    cudaGetSymbolAddress((void**)&wvh, g_Wvh); cudaGetSymbolAddress((void**)&wvl, g_Wvl);
    cudaGetSymbolAddress((void**)&woh, g_Woh); cudaGetSymbolAddress((void**)&wol, g_Wol);
    cudaGetSymbolAddress((void**)&qhh, g_Qhh); cudaGetSymbolAddress((void**)&qhl, g_Qhl);
    cudaGetSymbolAddress((void**)&khh, g_Khh); cudaGetSymbolAddress((void**)&khl, g_Khl);
    cudaGetSymbolAddress((void**)&vhh, g_Vhh); cudaGetSymbolAddress((void**)&vhl, g_Vhl);
    cudaGetSymbolAddress((void**)&ohh, g_Ohh); cudaGetSymbolAddress((void**)&ohl, g_Ohl);

    static bool attr_done = false;
    if (!attr_done) {
        cudaFuncSetAttribute(tc_gemm_kernel,
                             cudaFuncAttributeMaxDynamicSharedMemorySize, GSMEM);
        cudaFuncSetAttribute(flash_mma_kernel,
                             cudaFuncAttributeMaxDynamicSharedMemorySize, FSMEM);
        attr_done = true;
    }

    dim3 gg(DMODEL / 256, SEQL / 128);   // (4, 32) = 128 CTAs

    // [0] all splits in one launch
    split_all_kernel<<<dim3((SEQL * DMODEL / 4) / 256, 1, 7), 256>>>(
        Q, K, V, WQ, WK, WV, WO,
        qih, qil, kih, kil, vih, vil,
        wqh, wql, wkh, wkl, wvh, wvl, woh, wol);

    // [1..3] projection GEMMs: Q,K 3-term; V 2-term
    tc_gemm_kernel<<<gg, 512, GSMEM>>>(qih, qil, wqh, wql, nullptr, qhh, qhl, 3);
    tc_gemm_kernel<<<gg, 512, GSMEM>>>(kih, kil, wkh, wkl, nullptr, khh, khl, 3);
    tc_gemm_kernel<<<gg, 512, GSMEM>>>(vih, vil, wvh, wvl, nullptr, vhh, vhl, 2);

    // [4] dummy (keeps flash at ncu launch index 5)
    idle_kernel<<<1, 32>>>();

    // [5] flash attention: 256 q-rows/CTA, 512 threads, grid (16, 16)
    flash_mma_kernel<<<dim3(SEQL / 256, NH), 512, FSMEM>>>(
        qhh, qhl, khh, khl, vhh, ohh, ohl);

    // [6] output projection: 2-term, fp32 out
    tc_gemm_kernel<<<gg, 512, GSMEM>>>(ohh, ohl, woh, wol, out, nullptr, nullptr, 2);
}

// round 15
// speedup vs baseline: 1.1575x; 1.1575x over previous
#include <cuda_runtime.h>
#include <cuda_fp16.h>
#include <cstdint>

#define SEQL 4096
#define DMODEL 1024
#define NH 16
#define DKH 64

// Scratch (allocation-free rule: static device globals) — all fp16 hi/lo
static __device__ __half g_Qih[SEQL * DMODEL], g_Qil[SEQL * DMODEL];
static __device__ __half g_Kih[SEQL * DMODEL], g_Kil[SEQL * DMODEL];
static __device__ __half g_Vih[SEQL * DMODEL], g_Vil[SEQL * DMODEL];
static __device__ __half g_Wqh[DMODEL * DMODEL], g_Wql[DMODEL * DMODEL];
static __device__ __half g_Wkh[DMODEL * DMODEL], g_Wkl[DMODEL * DMODEL];
static __device__ __half g_Wvh[DMODEL * DMODEL], g_Wvl[DMODEL * DMODEL];
static __device__ __half g_Woh[DMODEL * DMODEL], g_Wol[DMODEL * DMODEL];
static __device__ __half g_Qhh[SEQL * DMODEL], g_Qhl[SEQL * DMODEL];
static __device__ __half g_Khh[SEQL * DMODEL], g_Khl[SEQL * DMODEL];
static __device__ __half g_Vhh[SEQL * DMODEL], g_Vhl[SEQL * DMODEL];
static __device__ __half g_Ohh[SEQL * DMODEL], g_Ohl[SEQL * DMODEL];

// ---------------- low-level helpers (base PTX only, no 'a' features) -------
__device__ __forceinline__ uint32_t smem_u32(const void* p) {
    uint32_t a;
    asm("{ .reg .u64 t; cvta.to.shared.u64 t, %1; cvt.u32.u64 %0, t; }" : "=r"(a) : "l"(p));
    return a;
}
__device__ __forceinline__ void cp16(uint32_t dst, const void* src) {
    asm volatile("cp.async.cg.shared.global [%0], [%1], 16;" :: "r"(dst), "l"(src));
}
__device__ __forceinline__ void cp_commit() {
    asm volatile("cp.async.commit_group;" ::: "memory");
}
__device__ __forceinline__ void ldmx4(uint32_t* r, uint32_t addr) {
    asm volatile("ldmatrix.sync.aligned.m8n8.x4.shared.b16 {%0,%1,%2,%3}, [%4];"
                 : "=r"(r[0]), "=r"(r[1]), "=r"(r[2]), "=r"(r[3]) : "r"(addr));
}
__device__ __forceinline__ void ldmx4t(uint32_t* r, uint32_t addr) {
    asm volatile("ldmatrix.sync.aligned.m8n8.x4.trans.shared.b16 {%0,%1,%2,%3}, [%4];"
                 : "=r"(r[0]), "=r"(r[1]), "=r"(r[2]), "=r"(r[3]) : "r"(addr));
}
// fp16 inputs, fp32 accumulate
__device__ __forceinline__ void mma16816(float* c, const uint32_t* a, const uint32_t* b) {
    asm volatile(
        "mma.sync.aligned.m16n8k16.row.col.f32.f16.f16.f32 "
        "{%0,%1,%2,%3}, {%4,%5,%6,%7}, {%8,%9}, {%0,%1,%2,%3};"
        : "+f"(c[0]), "+f"(c[1]), "+f"(c[2]), "+f"(c[3])
        : "r"(a[0]), "r"(a[1]), "r"(a[2]), "r"(a[3]), "r"(b[0]), "r"(b[1]));
}
// fp32 pair -> fp16 hi frag + fp16 residual frag
__device__ __forceinline__ void pconv(float s0, float s1, uint32_t& ph, uint32_t& pl) {
    __half2 h2 = __floats2half2_rn(s0, s1);
    __half2 l2 = __floats2half2_rn(s0 - __half2float(__low2half(h2)),
                                   s1 - __half2float(__high2half(h2)));
    ph = *(uint32_t*)&h2;
    pl = *(uint32_t*)&l2;
}
// fp32 pair -> single fp16x2 frag
__device__ __forceinline__ uint32_t packh2(float s0, float s1) {
    __half2 h2 = __floats2half2_rn(s0, s1);
    return *(uint32_t*)&h2;
}

// ---------------------------------------------------------------------------
// Merged split kernel. z<3: inputs Q/K/V (4 floats/thread).
// z in 3..6: weights WQ/WK/WV/WO -> Bt[n][k] (1 element/thread).
// ---------------------------------------------------------------------------
__global__ void split_all_kernel(
    const float* __restrict__ Q, const float* __restrict__ K,
    const float* __restrict__ V,
    const float* __restrict__ WQ, const float* __restrict__ WK,
    const float* __restrict__ WV, const float* __restrict__ WO,
    __half* __restrict__ Qih, __half* __restrict__ Qil,
    __half* __restrict__ Kih, __half* __restrict__ Kil,
    __half* __restrict__ Vih, __half* __restrict__ Vil,
    __half* __restrict__ Wqh, __half* __restrict__ Wql,
    __half* __restrict__ Wkh, __half* __restrict__ Wkl,
    __half* __restrict__ Wvh, __half* __restrict__ Wvl,
    __half* __restrict__ Woh, __half* __restrict__ Wol)
{
    const int z = blockIdx.z;
    if (z < 3) {
        const float* X = (z == 0) ? Q : (z == 1) ? K : V;
        __half* H = (z == 0) ? Qih : (z == 1) ? Kih : Vih;
        __half* L = (z == 0) ? Qil : (z == 1) ? Kil : Vil;
        int i = (blockIdx.x * blockDim.x + threadIdx.x) * 4;
        float4 v = *(const float4*)(X + i);
        float vv[4] = {v.x, v.y, v.z, v.w};
        __half h[4], l[4];
#pragma unroll
        for (int j = 0; j < 4; j++) {
            h[j] = __float2half_rn(vv[j]);
            l[j] = __float2half_rn(vv[j] - __half2float(h[j]));
        }
        *(__half2*)(H + i)     = __half2(h[0], h[1]);
        *(__half2*)(H + i + 2) = __half2(h[2], h[3]);
        *(__half2*)(L + i)     = __half2(l[0], l[1]);
        *(__half2*)(L + i + 2) = __half2(l[2], l[3]);
    } else {
        const int w = z - 3;
        const float* W = (w == 0) ? WQ : (w == 1) ? WK : (w == 2) ? WV : WO;
        __half* H = (w == 0) ? Wqh : (w == 1) ? Wkh : (w == 2) ? Wvh : Woh;
        __half* L = (w == 0) ? Wql : (w == 1) ? Wkl : (w == 2) ? Wvl : Wol;
        int idx = blockIdx.x * blockDim.x + threadIdx.x;   // = n*1024 + k
        int n = idx >> 10, k = idx & 1023;
        float v = (w < 3) ? W[(n >> 6) * (DMODEL * DKH) + k * DKH + (n & 63)]
                          : W[k * DMODEL + n];
        __half h = __float2half_rn(v);
        H[idx] = h;
        L[idx] = __float2half_rn(v - __half2float(h));
    }
}

// ---------------------------------------------------------------------------
// fp16 GEMM on mma.sync:  C = A @ Bt^T.  (unchanged from R13)
// terms==3: AhBh + AhBl + AlBh; terms==2: AhBh + AlBh.
// CTA tile M=128 x N=256, BK=32, 512 threads, 3-stage cp.async pipeline.
// ---------------------------------------------------------------------------
#define OA_H 0
#define OA_L 10240
#define OB_H 20480
#define OB_L 40960
#define GSTG 61440
#define GSMEM (3 * GSTG)

__global__ __launch_bounds__(512, 1) void tc_gemm_kernel(
    const __half* __restrict__ Ah, const __half* __restrict__ Al,
    const __half* __restrict__ Bh, const __half* __restrict__ Bl,
    float* __restrict__ Cf,
    __half* __restrict__ Ch, __half* __restrict__ Cl, int terms)
{
    extern __shared__ char smem[];
    const uint32_t sb = smem_u32(smem);
    const int tid = threadIdx.x;
    const int wid = tid >> 5, lane = tid & 31;
    const int m0 = blockIdx.y * 128;
    const int n0 = blockIdx.x * 256;
    const int wm0 = (wid & 1) * 64;
    const int wn0 = (wid >> 1) * 32;

    float acc[4][4][4];
#pragma unroll
    for (int i = 0; i < 4; i++)
#pragma unroll
        for (int j = 0; j < 4; j++)
#pragma unroll
            for (int t = 0; t < 4; t++) acc[i][j][t] = 0.f;

    const int ar = tid >> 2, ac = tid & 3;
    const int br = tid >> 1, bc = (2 * tid) & 3;

    auto load_stage = [&](int st, int k0) {
        uint32_t base = sb + st * GSTG;
        const __half* ga  = Ah + (m0 + ar) * DMODEL + k0 + ac * 8;
        const __half* gal = Al + (m0 + ar) * DMODEL + k0 + ac * 8;
        const __half* gb  = Bh + (n0 + br) * DMODEL + k0 + bc * 8;
        uint32_t soA = ar * 80 + ac * 16;
        uint32_t soB = br * 80 + bc * 16;
        cp16(base + OA_H + soA, ga);
        cp16(base + OA_L + soA, gal);
        cp16(base + OB_H + soB, gb);   cp16(base + OB_H + soB + 16, gb + 8);
        if (terms == 3) {
            const __half* gbl = Bl + (n0 + br) * DMODEL + k0 + bc * 8;
            cp16(base + OB_L + soB, gbl);  cp16(base + OB_L + soB + 16, gbl + 8);
        }
    };

    load_stage(0, 0);
    cp_commit();
    load_stage(1, 32);
    cp_commit();

    for (int kc = 0; kc < 32; kc++) {
        asm volatile("cp.async.wait_group 1;" ::: "memory");
        __syncthreads();
        if (kc + 2 < 32) load_stage((kc + 2) % 3, (kc + 2) * 32);
        cp_commit();

        uint32_t base = sb + (kc % 3) * GSTG;
#pragma unroll
        for (int k16 = 0; k16 < 32; k16 += 16) {
            uint32_t bh[4][2], bl[4][2];
#pragma unroll
            for (int bt = 0; bt < 2; bt++) {
                int nrow = wn0 + bt * 16 + (lane & 7) + ((lane >> 4) << 3);
                int kcol = k16 + ((lane >> 3) & 1) * 8;
                uint32_t ad = base + OB_H + nrow * 80 + kcol * 2;
                uint32_t r[4];
                ldmx4(r, ad);
                bh[bt * 2][0] = r[0]; bh[bt * 2][1] = r[1];
                bh[bt * 2 + 1][0] = r[2]; bh[bt * 2 + 1][1] = r[3];
                if (terms == 3) {
                    ldmx4(r, ad + (OB_L - OB_H));
                    bl[bt * 2][0] = r[0]; bl[bt * 2][1] = r[1];
                    bl[bt * 2 + 1][0] = r[2]; bl[bt * 2 + 1][1] = r[3];
                }
            }
#pragma unroll
            for (int mt = 0; mt < 4; mt++) {
                int mrow = wm0 + mt * 16 + (lane & 15);
                int kcol = k16 + (lane >> 4) * 8;
                uint32_t ad = base + OA_H + mrow * 80 + kcol * 2;
                uint32_t ah[4], al[4];
                ldmx4(ah, ad);
                ldmx4(al, ad + (OA_L - OA_H));
#pragma unroll
                for (int nt = 0; nt < 4; nt++) mma16816(acc[mt][nt], ah, bh[nt]);
#pragma unroll
                for (int nt = 0; nt < 4; nt++) mma16816(acc[mt][nt], al, bh[nt]);
                if (terms == 3) {
#pragma unroll
                    for (int nt = 0; nt < 4; nt++) mma16816(acc[mt][nt], ah, bl[nt]);
                }
            }
        }
    }

    const int er = lane >> 2;
    const int ec = 2 * (lane & 3);
    if (Ch == nullptr) {
#pragma unroll
        for (int mt = 0; mt < 4; mt++)
#pragma unroll
            for (int nt = 0; nt < 4; nt++) {
                int r = m0 + wm0 + mt * 16 + er;
                int c = n0 + wn0 + nt * 8 + ec;
                *(float2*)(Cf + r * DMODEL + c) = make_float2(acc[mt][nt][0], acc[mt][nt][1]);
                *(float2*)(Cf + (r + 8) * DMODEL + c) = make_float2(acc[mt][nt][2], acc[mt][nt][3]);
            }
    } else {
#pragma unroll
        for (int mt = 0; mt < 4; mt++)
#pragma unroll
            for (int nt = 0; nt < 4; nt++) {
                int r = m0 + wm0 + mt * 16 + er;
                int c = n0 + wn0 + nt * 8 + ec;
                uint32_t h0, l0, h1, l1;
                pconv(acc[mt][nt][0], acc[mt][nt][1], h0, l0);
                pconv(acc[mt][nt][2], acc[mt][nt][3], h1, l1);
                *(uint32_t*)(Ch + r * DMODEL + c) = h0;
                *(uint32_t*)(Cl + r * DMODEL + c) = l0;
                *(uint32_t*)(Ch + (r + 8) * DMODEL + c) = h1;
                *(uint32_t*)(Cl + (r + 8) * DMODEL + c) = l1;
            }
    }
}

// ---------------------------------------------------------------------------
// Flash attention on mma.sync, causal. fp16 numerics (R13 geometry):
//   S = Qh Kh^T + Qh Kl^T + Ql Kh^T ; O += P V (single fp16)
// CTA = 128 q-rows, 256 threads, 3-stage KV pipeline, 104KB smem
// (2 CTAs/SM co-residency). CAUSAL WORK PAIRING: CTA p processes q-tiles
// p and 31-p sequentially -> every CTA does exactly 33 kt-iterations ->
// one uniform wave (256 CTAs over 296 slots), no tail imbalance.
// ---------------------------------------------------------------------------
#define FSTG 24576
#define FSMEM (32768 + 3 * FSTG)

__global__ __launch_bounds__(256, 1) void flash_mma_kernel(
    const __half* __restrict__ Qh, const __half* __restrict__ Ql,
    const __half* __restrict__ Kh, const __half* __restrict__ Kl,
    const __half* __restrict__ Vh,
    __half* __restrict__ Oh, __half* __restrict__ Ol)
{
    extern __shared__ char fsm[];
    const uint32_t sb = smem_u32(fsm);
    const int tid = threadIdx.x;
    const int lane = tid & 31, wid = tid >> 5;
    const int h = blockIdx.y;
    const int pr = blockIdx.x;                    // pair index 0..15
    const int cb = h * DKH;
    const int wq = wid * 16;
    const int lr8 = lane & 7, lg = lane >> 3;

    auto load_kv = [&](int stage, int s0) {
        uint32_t base = sb + 32768 + stage * FSTG;
#pragma unroll
        for (int i = 0; i < 2; i++) {
            int idx = i * 256 + tid;
            int r = idx >> 3, u = idx & 7;
            uint32_t so = r * 128 + ((u ^ (r & 7)) << 4);
            int go = (s0 + r) * DMODEL + cb + u * 8;
            cp16(base + so, Kh + go);
            cp16(base + 8192 + so, Kl + go);
            cp16(base + 16384 + so, Vh + go);
        }
    };

    for (int half = 0; half < 2; half++) {
        const int qt = (half == 0) ? (31 - pr) : pr;   // long tile first
        const int q0 = qt * 128;
        const int nk = 2 * (qt + 1);

        // group 0: Q(h,l) + KV stage 0
#pragma unroll
        for (int i = 0; i < 4; i++) {
            int idx = i * 256 + tid;
            int r = idx >> 3, u = idx & 7;
            uint32_t so = r * 128 + ((u ^ (r & 7)) << 4);
            int go = (q0 + r) * DMODEL + cb + u * 8;
            cp16(sb + so, Qh + go);
            cp16(sb + 16384 + so, Ql + go);
        }
        load_kv(0, 0);
        cp_commit();
        if (nk > 1) load_kv(1, 64);
        cp_commit();

        float m_lo = -1e30f, m_hi = -1e30f, l_lo = 0.f, l_hi = 0.f;
        float oacc[8][4];
#pragma unroll
        for (int t = 0; t < 8; t++)
#pragma unroll
            for (int e = 0; e < 4; e++) oacc[t][e] = 0.f;
        uint32_t qha[4][4], qla[4][4];

        for (int kt = 0; kt < nk; kt++) {
            asm volatile("cp.async.wait_group 1;" ::: "memory");
            __syncthreads();
            if (kt + 2 < nk) load_kv((kt + 2) % 3, (kt + 2) * 64);
            cp_commit();

            if (kt == 0) {
#pragma unroll
                for (int ks = 0; ks < 4; ks++) {
                    int qr = wq + (lg & 1) * 8 + lr8;
                    int u = 2 * ks + (lg >> 1);
                    uint32_t a = sb + qr * 128 + ((u ^ (qr & 7)) << 4);
                    ldmx4(qha[ks], a);
                    ldmx4(qla[ks], a + 16384);
                }
            }

            const uint32_t kvb = sb + 32768 + (kt % 3) * FSTG;
            const bool skip = (kt * 64 > q0 + wq + 15);
            if (!skip) {
                float sacc[8][4];
#pragma unroll
                for (int t = 0; t < 8; t++)
#pragma unroll
                    for (int e = 0; e < 4; e++) sacc[t][e] = 0.f;

#pragma unroll
                for (int ks = 0; ks < 4; ks++) {
                    uint32_t kh[4][4], kl[4][4];
#pragma unroll
                    for (int pj = 0; pj < 4; pj++) {
                        int kr = pj * 16 + (lg >> 1) * 8 + lr8;
                        int u = 2 * ks + (lg & 1);
                        uint32_t ka = kvb + kr * 128 + ((u ^ (kr & 7)) << 4);
                        ldmx4(kh[pj], ka);
                        ldmx4(kl[pj], ka + 8192);
                    }
#pragma unroll
                    for (int pj = 0; pj < 4; pj++) {
                        mma16816(sacc[2 * pj], qha[ks], kh[pj]);
                        mma16816(sacc[2 * pj + 1], qha[ks], kh[pj] + 2);
                    }
#pragma unroll
                    for (int pj = 0; pj < 4; pj++) {
                        mma16816(sacc[2 * pj], qha[ks], kl[pj]);
                        mma16816(sacc[2 * pj + 1], qha[ks], kl[pj] + 2);
                    }
#pragma unroll
                    for (int pj = 0; pj < 4; pj++) {
                        mma16816(sacc[2 * pj], qla[ks], kh[pj]);
                        mma16816(sacc[2 * pj + 1], qla[ks], kh[pj] + 2);
                    }
                }

                const int gr_lo = q0 + wq + (lane >> 2);
                const bool maskt = (kt * 64 + 63 > q0 + wq);
#pragma unroll
                for (int t = 0; t < 8; t++)
#pragma unroll
                    for (int e = 0; e < 4; e++) {
                        float s = sacc[t][e] * 0.125f;
                        if (maskt) {
                            int col = kt * 64 + t * 8 + 2 * (lane & 3) + (e & 1);
                            int row = gr_lo + ((e >> 1) << 3);
                            if (col > row) s = -1e9f;
                        }
                        sacc[t][e] = s;
                    }

                float rx_lo = -1e30f, rx_hi = -1e30f;
#pragma unroll
                for (int t = 0; t < 8; t++) {
                    rx_lo = fmaxf(rx_lo, fmaxf(sacc[t][0], sacc[t][1]));
                    rx_hi = fmaxf(rx_hi, fmaxf(sacc[t][2], sacc[t][3]));
                }
                rx_lo = fmaxf(rx_lo, __shfl_xor_sync(0xffffffffu, rx_lo, 1));
                rx_lo = fmaxf(rx_lo, __shfl_xor_sync(0xffffffffu, rx_lo, 2));
                rx_hi = fmaxf(rx_hi, __shfl_xor_sync(0xffffffffu, rx_hi, 1));
                rx_hi = fmaxf(rx_hi, __shfl_xor_sync(0xffffffffu, rx_hi, 2));

                float mn_lo = fmaxf(m_lo, rx_lo);
                float mn_hi = fmaxf(m_hi, rx_hi);
                float al_lo = __expf(m_lo - mn_lo);
                float al_hi = __expf(m_hi - mn_hi);
                m_lo = mn_lo; m_hi = mn_hi;

                float sm_lo = 0.f, sm_hi = 0.f;
#pragma unroll
                for (int t = 0; t < 8; t++) {
                    sacc[t][0] = __expf(sacc[t][0] - m_lo);
                    sacc[t][1] = __expf(sacc[t][1] - m_lo);
                    sacc[t][2] = __expf(sacc[t][2] - m_hi);
                    sacc[t][3] = __expf(sacc[t][3] - m_hi);
                    sm_lo += sacc[t][0] + sacc[t][1];
                    sm_hi += sacc[t][2] + sacc[t][3];
                }
                sm_lo += __shfl_xor_sync(0xffffffffu, sm_lo, 1);
                sm_lo += __shfl_xor_sync(0xffffffffu, sm_lo, 2);
                sm_hi += __shfl_xor_sync(0xffffffffu, sm_hi, 1);
                sm_hi += __shfl_xor_sync(0xffffffffu, sm_hi, 2);
                l_lo = l_lo * al_lo + sm_lo;
                l_hi = l_hi * al_hi + sm_hi;
#pragma unroll
                for (int t = 0; t < 8; t++) {
                    oacc[t][0] *= al_lo; oacc[t][1] *= al_lo;
                    oacc[t][2] *= al_hi; oacc[t][3] *= al_hi;
                }

#pragma unroll
                for (int ks = 0; ks < 4; ks++) {
                    uint32_t ph[4];
                    int t0 = 2 * ks, t1 = 2 * ks + 1;
                    ph[0] = packh2(sacc[t0][0], sacc[t0][1]);
                    ph[1] = packh2(sacc[t0][2], sacc[t0][3]);
                    ph[2] = packh2(sacc[t1][0], sacc[t1][1]);
                    ph[3] = packh2(sacc[t1][2], sacc[t1][3]);

                    uint32_t vh[4][4];
#pragma unroll
                    for (int pj = 0; pj < 4; pj++) {
                        int vr = ks * 16 + (lg & 1) * 8 + lr8;
                        int u = 2 * pj + (lg >> 1);
                        uint32_t va = kvb + 16384 + vr * 128 + ((u ^ (vr & 7)) << 4);
                        ldmx4t(vh[pj], va);
                    }
#pragma unroll
                    for (int pj = 0; pj < 4; pj++) {
                        mma16816(oacc[2 * pj], ph, vh[pj]);
                        mma16816(oacc[2 * pj + 1], ph, vh[pj] + 2);
                    }
                }
            }
        }

        // ---- epilogue for this half
        const float inv_lo = 1.0f / l_lo;
        const float inv_hi = 1.0f / l_hi;
        const int gr_lo = q0 + wq + (lane >> 2);
#pragma unroll
        for (int t = 0; t < 8; t++) {
            int c = cb + t * 8 + 2 * (lane & 3);
            {
                float o0 = oacc[t][0] * inv_lo, o1 = oacc[t][1] * inv_lo;
                uint32_t hh, ll;
                pconv(o0, o1, hh, ll);
                *(uint32_t*)(Oh + gr_lo * DMODEL + c) = hh;
                *(uint32_t*)(Ol + gr_lo * DMODEL + c) = ll;
            }
            {
                float o0 = oacc[t][2] * inv_hi, o1 = oacc[t][3] * inv_hi;
                uint32_t hh, ll;
                pconv(o0, o1, hh, ll);
                *(uint32_t*)(Oh + (gr_lo + 8) * DMODEL + c) = hh;
                *(uint32_t*)(Ol + (gr_lo + 8) * DMODEL + c) = ll;
            }
        }

        // Drain pipeline + fence all readers before half 1 rewrites smem
        if (half == 0) {
            asm volatile("cp.async.wait_group 0;" ::: "memory");
            __syncthreads();
        }
    }
}

// ---------------------------------------------------------------------------
extern "C" void kernel_launch(void* const* d_in, const int* in_sizes, int n_in,
                              void* d_out, int out_size)
{
    const float* Q  = (const float*)d_in[0];
    const float* K  = (const float*)d_in[1];
    const float* V  = (const float*)d_in[2];
    const float* WQ = (const float*)d_in[3];
    const float* WK = (const float*)d_in[4];
    const float* WV = (const float*)d_in[5];
    const float* WO = (const float*)d_in[6];
    float* out = (float*)d_out;

    __half *qih, *qil, *kih, *kil, *vih, *vil;
    __half *wqh, *wql, *wkh, *wkl, *wvh, *wvl, *woh, *wol;
    __half *qhh, *qhl, *khh, *khl, *vhh, *vhl, *ohh, *ohl;
    cudaGetSymbolAddress((void**)&qih, g_Qih); cudaGetSymbolAddress((void**)&qil, g_Qil);
    cudaGetSymbolAddress((void**)&kih, g_Kih); cudaGetSymbolAddress((void**)&kil, g_Kil);
    cudaGetSymbolAddress((void**)&vih, g_Vih); cudaGetSymbolAddress((void**)&vil, g_Vil);
    cudaGetSymbolAddress((void**)&wqh, g_Wqh); cudaGetSymbolAddress((void**)&wql, g_Wql);
    cudaGetSymbolAddress((void**)&wkh, g_Wkh); cudaGetSymbolAddress((void**)&wkl, g_Wkl);
    cudaGetSymbolAddress((void**)&wvh, g_Wvh); cudaGetSymbolAddress((void**)&wvl, g_Wvl);
    cudaGetSymbolAddress((void**)&woh, g_Woh); cudaGetSymbolAddress((void**)&wol, g_Wol);
    cudaGetSymbolAddress((void**)&qhh, g_Qhh); cudaGetSymbolAddress((void**)&qhl, g_Qhl);
    cudaGetSymbolAddress((void**)&khh, g_Khh); cudaGetSymbolAddress((void**)&khl, g_Khl);
    cudaGetSymbolAddress((void**)&vhh, g_Vhh); cudaGetSymbolAddress((void**)&vhl, g_Vhl);
    cudaGetSymbolAddress((void**)&ohh, g_Ohh); cudaGetSymbolAddress((void**)&ohl, g_Ohl);

    static bool attr_done = false;
    if (!attr_done) {
        cudaFuncSetAttribute(tc_gemm_kernel,
                             cudaFuncAttributeMaxDynamicSharedMemorySize, GSMEM);
        cudaFuncSetAttribute(flash_mma_kernel,
                             cudaFuncAttributeMaxDynamicSharedMemorySize, FSMEM);
        attr_done = true;
    }

    dim3 gg(DMODEL / 256, SEQL / 128);   // (4, 32) = 128 CTAs

    // [0] all splits in one launch
    split_all_kernel<<<dim3((SEQL * DMODEL / 4) / 256, 1, 7), 256>>>(
        Q, K, V, WQ, WK, WV, WO,
        qih, qil, kih, kil, vih, vil,
        wqh, wql, wkh, wkl, wvh, wvl, woh, wol);

    // [1..3] projection GEMMs: Q,K 3-term; V 2-term
    tc_gemm_kernel<<<gg, 512, GSMEM>>>(qih, qil, wqh, wql, nullptr, qhh, qhl, 3);
    tc_gemm_kernel<<<gg, 512, GSMEM>>>(kih, kil, wkh, wkl, nullptr, khh, khl, 3);
    tc_gemm_kernel<<<gg, 512, GSMEM>>>(vih, vil, wvh, wvl, nullptr, vhh, vhl, 2);

    // [4] flash attention: paired q-tiles (p, 31-p), uniform 33 iters/CTA
    flash_mma_kernel<<<dim3(16, NH), 256, FSMEM>>>(
        qhh, qhl, khh, khl, vhh, ohh, ohl);

    // [5] output projection: 2-term, fp32 out
    tc_gemm_kernel<<<gg, 512, GSMEM>>>(ohh, ohl, woh, wol, out, nullptr, nullptr, 2);
}

// round 16
// speedup vs baseline: 1.1640x; 1.0056x over previous
#include <cuda_runtime.h>
#include <cuda_fp16.h>
#include <cstdint>

#define SEQL 4096
#define DMODEL 1024
#define NH 16
#define DKH 64

// Scratch (allocation-free rule: static device globals) — all fp16 hi/lo
static __device__ __half g_Qih[SEQL * DMODEL], g_Qil[SEQL * DMODEL];
static __device__ __half g_Kih[SEQL * DMODEL], g_Kil[SEQL * DMODEL];
static __device__ __half g_Vih[SEQL * DMODEL], g_Vil[SEQL * DMODEL];
static __device__ __half g_Wqh[DMODEL * DMODEL], g_Wql[DMODEL * DMODEL];
static __device__ __half g_Wkh[DMODEL * DMODEL], g_Wkl[DMODEL * DMODEL];
static __device__ __half g_Wvh[DMODEL * DMODEL], g_Wvl[DMODEL * DMODEL];
static __device__ __half g_Woh[DMODEL * DMODEL], g_Wol[DMODEL * DMODEL];
static __device__ __half g_Qhh[SEQL * DMODEL], g_Qhl[SEQL * DMODEL];
static __device__ __half g_Khh[SEQL * DMODEL], g_Khl[SEQL * DMODEL];
static __device__ __half g_Vhh[SEQL * DMODEL], g_Vhl[SEQL * DMODEL];
static __device__ __half g_Ohh[SEQL * DMODEL], g_Ohl[SEQL * DMODEL];

// ---------------- low-level helpers (base PTX only, no 'a' features) -------
__device__ __forceinline__ uint32_t smem_u32(const void* p) {
    uint32_t a;
    asm("{ .reg .u64 t; cvta.to.shared.u64 t, %1; cvt.u32.u64 %0, t; }" : "=r"(a) : "l"(p));
    return a;
}
__device__ __forceinline__ void cp16(uint32_t dst, const void* src) {
    asm volatile("cp.async.cg.shared.global [%0], [%1], 16;" :: "r"(dst), "l"(src));
}
__device__ __forceinline__ void cp_commit() {
    asm volatile("cp.async.commit_group;" ::: "memory");
}
__device__ __forceinline__ void ldmx4(uint32_t* r, uint32_t addr) {
    asm volatile("ldmatrix.sync.aligned.m8n8.x4.shared.b16 {%0,%1,%2,%3}, [%4];"
                 : "=r"(r[0]), "=r"(r[1]), "=r"(r[2]), "=r"(r[3]) : "r"(addr));
}
__device__ __forceinline__ void ldmx4t(uint32_t* r, uint32_t addr) {
    asm volatile("ldmatrix.sync.aligned.m8n8.x4.trans.shared.b16 {%0,%1,%2,%3}, [%4];"
                 : "=r"(r[0]), "=r"(r[1]), "=r"(r[2]), "=r"(r[3]) : "r"(addr));
}
// fp16 inputs, fp32 accumulate
__device__ __forceinline__ void mma16816(float* c, const uint32_t* a, const uint32_t* b) {
    asm volatile(
        "mma.sync.aligned.m16n8k16.row.col.f32.f16.f16.f32 "
        "{%0,%1,%2,%3}, {%4,%5,%6,%7}, {%8,%9}, {%0,%1,%2,%3};"
        : "+f"(c[0]), "+f"(c[1]), "+f"(c[2]), "+f"(c[3])
        : "r"(a[0]), "r"(a[1]), "r"(a[2]), "r"(a[3]), "r"(b[0]), "r"(b[1]));
}
// fp32 pair -> fp16 hi frag + fp16 residual frag
__device__ __forceinline__ void pconv(float s0, float s1, uint32_t& ph, uint32_t& pl) {
    __half2 h2 = __floats2half2_rn(s0, s1);
    __half2 l2 = __floats2half2_rn(s0 - __half2float(__low2half(h2)),
                                   s1 - __half2float(__high2half(h2)));
    ph = *(uint32_t*)&h2;
    pl = *(uint32_t*)&l2;
}
// fp32 pair -> single fp16x2 frag
__device__ __forceinline__ uint32_t packh2(float s0, float s1) {
    __half2 h2 = __floats2half2_rn(s0, s1);
    return *(uint32_t*)&h2;
}

// ---------------------------------------------------------------------------
// Merged split kernel. z<3: inputs Q/K/V (4 floats/thread).
// z in 3..6: weights WQ/WK/WV/WO -> Bt[n][k] (1 element/thread).
// ---------------------------------------------------------------------------
__global__ void split_all_kernel(
    const float* __restrict__ Q, const float* __restrict__ K,
    const float* __restrict__ V,
    const float* __restrict__ WQ, const float* __restrict__ WK,
    const float* __restrict__ WV, const float* __restrict__ WO,
    __half* __restrict__ Qih, __half* __restrict__ Qil,
    __half* __restrict__ Kih, __half* __restrict__ Kil,
    __half* __restrict__ Vih, __half* __restrict__ Vil,
    __half* __restrict__ Wqh, __half* __restrict__ Wql,
    __half* __restrict__ Wkh, __half* __restrict__ Wkl,
    __half* __restrict__ Wvh, __half* __restrict__ Wvl,
    __half* __restrict__ Woh, __half* __restrict__ Wol)
{
    const int z = blockIdx.z;
    if (z < 3) {
        const float* X = (z == 0) ? Q : (z == 1) ? K : V;
        __half* H = (z == 0) ? Qih : (z == 1) ? Kih : Vih;
        __half* L = (z == 0) ? Qil : (z == 1) ? Kil : Vil;
        int i = (blockIdx.x * blockDim.x + threadIdx.x) * 4;
        float4 v = *(const float4*)(X + i);
        float vv[4] = {v.x, v.y, v.z, v.w};
        __half h[4], l[4];
#pragma unroll
        for (int j = 0; j < 4; j++) {
            h[j] = __float2half_rn(vv[j]);
            l[j] = __float2half_rn(vv[j] - __half2float(h[j]));
        }
        *(__half2*)(H + i)     = __half2(h[0], h[1]);
        *(__half2*)(H + i + 2) = __half2(h[2], h[3]);
        *(__half2*)(L + i)     = __half2(l[0], l[1]);
        *(__half2*)(L + i + 2) = __half2(l[2], l[3]);
    } else {
        const int w = z - 3;
        const float* W = (w == 0) ? WQ : (w == 1) ? WK : (w == 2) ? WV : WO;
        __half* H = (w == 0) ? Wqh : (w == 1) ? Wkh : (w == 2) ? Wvh : Woh;
        __half* L = (w == 0) ? Wql : (w == 1) ? Wkl : (w == 2) ? Wvl : Wol;
        int idx = blockIdx.x * blockDim.x + threadIdx.x;   // = n*1024 + k
        int n = idx >> 10, k = idx & 1023;
        float v = (w < 3) ? W[(n >> 6) * (DMODEL * DKH) + k * DKH + (n & 63)]
                          : W[k * DMODEL + n];
        __half h = __float2half_rn(v);
        H[idx] = h;
        L[idx] = __float2half_rn(v - __half2float(h));
    }
}

// ---------------------------------------------------------------------------
// Shared fp16 GEMM body (mma.sync):  C = A @ Bt^T for one 128x256 tile.
// terms==3: AhBh + AhBl + AlBh; terms==2: AhBh + AlBh.
// 512 threads, BK=32, 3-stage cp.async pipeline.
// ---------------------------------------------------------------------------
#define OA_H 0
#define OA_L 10240
#define OB_H 20480
#define OB_L 40960
#define GSTG 61440
#define GSMEM (3 * GSTG)

__device__ __forceinline__ void gemm_body(
    const __half* __restrict__ Ah, const __half* __restrict__ Al,
    const __half* __restrict__ Bh, const __half* __restrict__ Bl,
    float* __restrict__ Cf, __half* __restrict__ Ch, __half* __restrict__ Cl,
    int terms, int m0, int n0, uint32_t sb, char* smem)
{
    const int tid = threadIdx.x;
    const int wid = tid >> 5, lane = tid & 31;
    const int wm0 = (wid & 1) * 64;
    const int wn0 = (wid >> 1) * 32;

    float acc[4][4][4];
#pragma unroll
    for (int i = 0; i < 4; i++)
#pragma unroll
        for (int j = 0; j < 4; j++)
#pragma unroll
            for (int t = 0; t < 4; t++) acc[i][j][t] = 0.f;

    const int ar = tid >> 2, ac = tid & 3;
    const int br = tid >> 1, bc = (2 * tid) & 3;

    auto load_stage = [&](int st, int k0) {
        uint32_t base = sb + st * GSTG;
        const __half* ga  = Ah + (m0 + ar) * DMODEL + k0 + ac * 8;
        const __half* gal = Al + (m0 + ar) * DMODEL + k0 + ac * 8;
        const __half* gb  = Bh + (n0 + br) * DMODEL + k0 + bc * 8;
        uint32_t soA = ar * 80 + ac * 16;
        uint32_t soB = br * 80 + bc * 16;
        cp16(base + OA_H + soA, ga);
        cp16(base + OA_L + soA, gal);
        cp16(base + OB_H + soB, gb);   cp16(base + OB_H + soB + 16, gb + 8);
        if (terms == 3) {
            const __half* gbl = Bl + (n0 + br) * DMODEL + k0 + bc * 8;
            cp16(base + OB_L + soB, gbl);  cp16(base + OB_L + soB + 16, gbl + 8);
        }
    };

    load_stage(0, 0);
    cp_commit();
    load_stage(1, 32);
    cp_commit();

    for (int kc = 0; kc < 32; kc++) {
        asm volatile("cp.async.wait_group 1;" ::: "memory");
        __syncthreads();
        if (kc + 2 < 32) load_stage((kc + 2) % 3, (kc + 2) * 32);
        cp_commit();

        uint32_t base = sb + (kc % 3) * GSTG;
#pragma unroll
        for (int k16 = 0; k16 < 32; k16 += 16) {
            uint32_t bh[4][2], bl[4][2];
#pragma unroll
            for (int bt = 0; bt < 2; bt++) {
                int nrow = wn0 + bt * 16 + (lane & 7) + ((lane >> 4) << 3);
                int kcol = k16 + ((lane >> 3) & 1) * 8;
                uint32_t ad = base + OB_H + nrow * 80 + kcol * 2;
                uint32_t r[4];
                ldmx4(r, ad);
                bh[bt * 2][0] = r[0]; bh[bt * 2][1] = r[1];
                bh[bt * 2 + 1][0] = r[2]; bh[bt * 2 + 1][1] = r[3];
                if (terms == 3) {
                    ldmx4(r, ad + (OB_L - OB_H));
                    bl[bt * 2][0] = r[0]; bl[bt * 2][1] = r[1];
                    bl[bt * 2 + 1][0] = r[2]; bl[bt * 2 + 1][1] = r[3];
                }
            }
#pragma unroll
            for (int mt = 0; mt < 4; mt++) {
                int mrow = wm0 + mt * 16 + (lane & 15);
                int kcol = k16 + (lane >> 4) * 8;
                uint32_t ad = base + OA_H + mrow * 80 + kcol * 2;
                uint32_t ah[4], al[4];
                ldmx4(ah, ad);
                ldmx4(al, ad + (OA_L - OA_H));
#pragma unroll
                for (int nt = 0; nt < 4; nt++) mma16816(acc[mt][nt], ah, bh[nt]);
#pragma unroll
                for (int nt = 0; nt < 4; nt++) mma16816(acc[mt][nt], al, bh[nt]);
                if (terms == 3) {
#pragma unroll
                    for (int nt = 0; nt < 4; nt++) mma16816(acc[mt][nt], ah, bl[nt]);
                }
            }
        }
    }

    const int er = lane >> 2;
    const int ec = 2 * (lane & 3);
    if (Ch == nullptr) {
#pragma unroll
        for (int mt = 0; mt < 4; mt++)
#pragma unroll
            for (int nt = 0; nt < 4; nt++) {
                int r = m0 + wm0 + mt * 16 + er;
                int c = n0 + wn0 + nt * 8 + ec;
                *(float2*)(Cf + r * DMODEL + c) = make_float2(acc[mt][nt][0], acc[mt][nt][1]);
                *(float2*)(Cf + (r + 8) * DMODEL + c) = make_float2(acc[mt][nt][2], acc[mt][nt][3]);
            }
    } else {
#pragma unroll
        for (int mt = 0; mt < 4; mt++)
#pragma unroll
            for (int nt = 0; nt < 4; nt++) {
                int r = m0 + wm0 + mt * 16 + er;
                int c = n0 + wn0 + nt * 8 + ec;
                uint32_t h0, l0, h1, l1;
                pconv(acc[mt][nt][0], acc[mt][nt][1], h0, l0);
                pconv(acc[mt][nt][2], acc[mt][nt][3], h1, l1);
                *(uint32_t*)(Ch + r * DMODEL + c) = h0;
                *(uint32_t*)(Cl + r * DMODEL + c) = l0;
                *(uint32_t*)(Ch + (r + 8) * DMODEL + c) = h1;
                *(uint32_t*)(Cl + (r + 8) * DMODEL + c) = l1;
            }
    }
}

// Fused Q/K/V projection GEMM: grid (12, 32). blockIdx.x>>2 selects the
// matrix (0=Q 3-term, 1=K 3-term, 2=V 2-term); blockIdx.x&3 selects n-block.
__global__ __launch_bounds__(512, 1) void tc_gemm_qkv_kernel(
    const __half* __restrict__ Qih, const __half* __restrict__ Qil,
    const __half* __restrict__ Kih, const __half* __restrict__ Kil,
    const __half* __restrict__ Vih, const __half* __restrict__ Vil,
    const __half* __restrict__ Wqh, const __half* __restrict__ Wql,
    const __half* __restrict__ Wkh, const __half* __restrict__ Wkl,
    const __half* __restrict__ Wvh, const __half* __restrict__ Wvl,
    __half* __restrict__ Qhh, __half* __restrict__ Qhl,
    __half* __restrict__ Khh, __half* __restrict__ Khl,
    __half* __restrict__ Vhh, __half* __restrict__ Vhl)
{
    extern __shared__ char smem[];
    const uint32_t sb = smem_u32(smem);
    const int mat = blockIdx.x >> 2;
    const int n0 = (blockIdx.x & 3) * 256;
    const int m0 = blockIdx.y * 128;
    const __half* Ah = (mat == 0) ? Qih : (mat == 1) ? Kih : Vih;
    const __half* Al = (mat == 0) ? Qil : (mat == 1) ? Kil : Vil;
    const __half* Bh = (mat == 0) ? Wqh : (mat == 1) ? Wkh : Wvh;
    const __half* Bl = (mat == 0) ? Wql : (mat == 1) ? Wkl : Wvl;
    __half* Ch = (mat == 0) ? Qhh : (mat == 1) ? Khh : Vhh;
    __half* Cl = (mat == 0) ? Qhl : (mat == 1) ? Khl : Vhl;
    const int terms = (mat < 2) ? 3 : 2;
    gemm_body(Ah, Al, Bh, Bl, nullptr, Ch, Cl, terms, m0, n0, sb, smem);
}

// Single GEMM (output projection): grid (4, 32), fp32 out, 2-term.
__global__ __launch_bounds__(512, 1) void tc_gemm_kernel(
    const __half* __restrict__ Ah, const __half* __restrict__ Al,
    const __half* __restrict__ Bh, const __half* __restrict__ Bl,
    float* __restrict__ Cf, int terms)
{
    extern __shared__ char smem[];
    const uint32_t sb = smem_u32(smem);
    gemm_body(Ah, Al, Bh, Bl, Cf, nullptr, nullptr, terms,
              blockIdx.y * 128, blockIdx.x * 256, sb, smem);
}

// ---------------------------------------------------------------------------
// Flash attention on mma.sync, causal (unchanged from R15).
// CTA = 128 q-rows, 256 threads, 3-stage KV pipeline, causal work pairing.
// ---------------------------------------------------------------------------
#define FSTG 24576
#define FSMEM (32768 + 3 * FSTG)

__global__ __launch_bounds__(256, 1) void flash_mma_kernel(
    const __half* __restrict__ Qh, const __half* __restrict__ Ql,
    const __half* __restrict__ Kh, const __half* __restrict__ Kl,
    const __half* __restrict__ Vh,
    __half* __restrict__ Oh, __half* __restrict__ Ol)
{
    extern __shared__ char fsm[];
    const uint32_t sb = smem_u32(fsm);
    const int tid = threadIdx.x;
    const int lane = tid & 31, wid = tid >> 5;
    const int h = blockIdx.y;
    const int pr = blockIdx.x;                    // pair index 0..15
    const int cb = h * DKH;
    const int wq = wid * 16;
    const int lr8 = lane & 7, lg = lane >> 3;

    auto load_kv = [&](int stage, int s0) {
        uint32_t base = sb + 32768 + stage * FSTG;
#pragma unroll
        for (int i = 0; i < 2; i++) {
            int idx = i * 256 + tid;
            int r = idx >> 3, u = idx & 7;
            uint32_t so = r * 128 + ((u ^ (r & 7)) << 4);
            int go = (s0 + r) * DMODEL + cb + u * 8;
            cp16(base + so, Kh + go);
            cp16(base + 8192 + so, Kl + go);
            cp16(base + 16384 + so, Vh + go);
        }
    };

    for (int half = 0; half < 2; half++) {
        const int qt = (half == 0) ? (31 - pr) : pr;   // long tile first
        const int q0 = qt * 128;
        const int nk = 2 * (qt + 1);

        // group 0: Q(h,l) + KV stage 0
#pragma unroll
        for (int i = 0; i < 4; i++) {
            int idx = i * 256 + tid;
            int r = idx >> 3, u = idx & 7;
            uint32_t so = r * 128 + ((u ^ (r & 7)) << 4);
            int go = (q0 + r) * DMODEL + cb + u * 8;
            cp16(sb + so, Qh + go);
            cp16(sb + 16384 + so, Ql + go);
        }
        load_kv(0, 0);
        cp_commit();
        if (nk > 1) load_kv(1, 64);
        cp_commit();

        float m_lo = -1e30f, m_hi = -1e30f, l_lo = 0.f, l_hi = 0.f;
        float oacc[8][4];
#pragma unroll
        for (int t = 0; t < 8; t++)
#pragma unroll
            for (int e = 0; e < 4; e++) oacc[t][e] = 0.f;
        uint32_t qha[4][4], qla[4][4];

        for (int kt = 0; kt < nk; kt++) {
            asm volatile("cp.async.wait_group 1;" ::: "memory");
            __syncthreads();
            if (kt + 2 < nk) load_kv((kt + 2) % 3, (kt + 2) * 64);
            cp_commit();

            if (kt == 0) {
#pragma unroll
                for (int ks = 0; ks < 4; ks++) {
                    int qr = wq + (lg & 1) * 8 + lr8;
                    int u = 2 * ks + (lg >> 1);
                    uint32_t a = sb + qr * 128 + ((u ^ (qr & 7)) << 4);
                    ldmx4(qha[ks], a);
                    ldmx4(qla[ks], a + 16384);
                }
            }

            const uint32_t kvb = sb + 32768 + (kt % 3) * FSTG;
            const bool skip = (kt * 64 > q0 + wq + 15);
            if (!skip) {
                float sacc[8][4];
#pragma unroll
                for (int t = 0; t < 8; t++)
#pragma unroll
                    for (int e = 0; e < 4; e++) sacc[t][e] = 0.f;

#pragma unroll
                for (int ks = 0; ks < 4; ks++) {
                    uint32_t kh[4][4], kl[4][4];
#pragma unroll
                    for (int pj = 0; pj < 4; pj++) {
                        int kr = pj * 16 + (lg >> 1) * 8 + lr8;
                        int u = 2 * ks + (lg & 1);
                        uint32_t ka = kvb + kr * 128 + ((u ^ (kr & 7)) << 4);
                        ldmx4(kh[pj], ka);
                        ldmx4(kl[pj], ka + 8192);
                    }
#pragma unroll
                    for (int pj = 0; pj < 4; pj++) {
                        mma16816(sacc[2 * pj], qha[ks], kh[pj]);
                        mma16816(sacc[2 * pj + 1], qha[ks], kh[pj] + 2);
                    }
#pragma unroll
                    for (int pj = 0; pj < 4; pj++) {
                        mma16816(sacc[2 * pj], qha[ks], kl[pj]);
                        mma16816(sacc[2 * pj + 1], qha[ks], kl[pj] + 2);
                    }
#pragma unroll
                    for (int pj = 0; pj < 4; pj++) {
                        mma16816(sacc[2 * pj], qla[ks], kh[pj]);
                        mma16816(sacc[2 * pj + 1], qla[ks], kh[pj] + 2);
                    }
                }

                const int gr_lo = q0 + wq + (lane >> 2);
                const bool maskt = (kt * 64 + 63 > q0 + wq);
#pragma unroll
                for (int t = 0; t < 8; t++)
#pragma unroll
                    for (int e = 0; e < 4; e++) {
                        float s = sacc[t][e] * 0.125f;
                        if (maskt) {
                            int col = kt * 64 + t * 8 + 2 * (lane & 3) + (e & 1);
                            int row = gr_lo + ((e >> 1) << 3);
                            if (col > row) s = -1e9f;
                        }
                        sacc[t][e] = s;
                    }

                float rx_lo = -1e30f, rx_hi = -1e30f;
#pragma unroll
                for (int t = 0; t < 8; t++) {
                    rx_lo = fmaxf(rx_lo, fmaxf(sacc[t][0], sacc[t][1]));
                    rx_hi = fmaxf(rx_hi, fmaxf(sacc[t][2], sacc[t][3]));
                }
                rx_lo = fmaxf(rx_lo, __shfl_xor_sync(0xffffffffu, rx_lo, 1));
                rx_lo = fmaxf(rx_lo, __shfl_xor_sync(0xffffffffu, rx_lo, 2));
                rx_hi = fmaxf(rx_hi, __shfl_xor_sync(0xffffffffu, rx_hi, 1));
                rx_hi = fmaxf(rx_hi, __shfl_xor_sync(0xffffffffu, rx_hi, 2));

                float mn_lo = fmaxf(m_lo, rx_lo);
                float mn_hi = fmaxf(m_hi, rx_hi);
                float al_lo = __expf(m_lo - mn_lo);
                float al_hi = __expf(m_hi - mn_hi);
                m_lo = mn_lo; m_hi = mn_hi;

                float sm_lo = 0.f, sm_hi = 0.f;
#pragma unroll
                for (int t = 0; t < 8; t++) {
                    sacc[t][0] = __expf(sacc[t][0] - m_lo);
                    sacc[t][1] = __expf(sacc[t][1] - m_lo);
                    sacc[t][2] = __expf(sacc[t][2] - m_hi);
                    sacc[t][3] = __expf(sacc[t][3] - m_hi);
                    sm_lo += sacc[t][0] + sacc[t][1];
                    sm_hi += sacc[t][2] + sacc[t][3];
                }
                sm_lo += __shfl_xor_sync(0xffffffffu, sm_lo, 1);
                sm_lo += __shfl_xor_sync(0xffffffffu, sm_lo, 2);
                sm_hi += __shfl_xor_sync(0xffffffffu, sm_hi, 1);
                sm_hi += __shfl_xor_sync(0xffffffffu, sm_hi, 2);
                l_lo = l_lo * al_lo + sm_lo;
                l_hi = l_hi * al_hi + sm_hi;
#pragma unroll
                for (int t = 0; t < 8; t++) {
                    oacc[t][0] *= al_lo; oacc[t][1] *= al_lo;
                    oacc[t][2] *= al_hi; oacc[t][3] *= al_hi;
                }

#pragma unroll
                for (int ks = 0; ks < 4; ks++) {
                    uint32_t ph[4];
                    int t0 = 2 * ks, t1 = 2 * ks + 1;
                    ph[0] = packh2(sacc[t0][0], sacc[t0][1]);
                    ph[1] = packh2(sacc[t0][2], sacc[t0][3]);
                    ph[2] = packh2(sacc[t1][0], sacc[t1][1]);
                    ph[3] = packh2(sacc[t1][2], sacc[t1][3]);

                    uint32_t vh[4][4];
#pragma unroll
                    for (int pj = 0; pj < 4; pj++) {
                        int vr = ks * 16 + (lg & 1) * 8 + lr8;
                        int u = 2 * pj + (lg >> 1);
                        uint32_t va = kvb + 16384 + vr * 128 + ((u ^ (vr & 7)) << 4);
                        ldmx4t(vh[pj], va);
                    }
#pragma unroll
                    for (int pj = 0; pj < 4; pj++) {
                        mma16816(oacc[2 * pj], ph, vh[pj]);
                        mma16816(oacc[2 * pj + 1], ph, vh[pj] + 2);
                    }
                }
            }
        }

        // ---- epilogue for this half
        const float inv_lo = 1.0f / l_lo;
        const float inv_hi = 1.0f / l_hi;
        const int gr_lo = q0 + wq + (lane >> 2);
#pragma unroll
        for (int t = 0; t < 8; t++) {
            int c = cb + t * 8 + 2 * (lane & 3);
            {
                float o0 = oacc[t][0] * inv_lo, o1 = oacc[t][1] * inv_lo;
                uint32_t hh, ll;
                pconv(o0, o1, hh, ll);
                *(uint32_t*)(Oh + gr_lo * DMODEL + c) = hh;
                *(uint32_t*)(Ol + gr_lo * DMODEL + c) = ll;
            }
            {
                float o0 = oacc[t][2] * inv_hi, o1 = oacc[t][3] * inv_hi;
                uint32_t hh, ll;
                pconv(o0, o1, hh, ll);
                *(uint32_t*)(Oh + (gr_lo + 8) * DMODEL + c) = hh;
                *(uint32_t*)(Ol + (gr_lo + 8) * DMODEL + c) = ll;
            }
        }

        // Drain pipeline + fence all readers before half 1 rewrites smem
        if (half == 0) {
            asm volatile("cp.async.wait_group 0;" ::: "memory");
            __syncthreads();
        }
    }
}

// ---------------------------------------------------------------------------
extern "C" void kernel_launch(void* const* d_in, const int* in_sizes, int n_in,
                              void* d_out, int out_size)
{
    const float* Q  = (const float*)d_in[0];
    const float* K  = (const float*)d_in[1];
    const float* V  = (const float*)d_in[2];
    const float* WQ = (const float*)d_in[3];
    const float* WK = (const float*)d_in[4];
    const float* WV = (const float*)d_in[5];
    const float* WO = (const float*)d_in[6];
    float* out = (float*)d_out;

    __half *qih, *qil, *kih, *kil, *vih, *vil;
    __half *wqh, *wql, *wkh, *wkl, *wvh, *wvl, *woh, *wol;
    __half *qhh, *qhl, *khh, *khl, *vhh, *vhl, *ohh, *ohl;
    cudaGetSymbolAddress((void**)&qih, g_Qih); cudaGetSymbolAddress((void**)&qil, g_Qil);
    cudaGetSymbolAddress((void**)&kih, g_Kih); cudaGetSymbolAddress((void**)&kil, g_Kil);
    cudaGetSymbolAddress((void**)&vih, g_Vih); cudaGetSymbolAddress((void**)&vil, g_Vil);
    cudaGetSymbolAddress((void**)&wqh, g_Wqh); cudaGetSymbolAddress((void**)&wql, g_Wql);
    cudaGetSymbolAddress((void**)&wkh, g_Wkh); cudaGetSymbolAddress((void**)&wkl, g_Wkl);
    cudaGetSymbolAddress((void**)&wvh, g_Wvh); cudaGetSymbolAddress((void**)&wvl, g_Wvl);
    cudaGetSymbolAddress((void**)&woh, g_Woh); cudaGetSymbolAddress((void**)&wol, g_Wol);
    cudaGetSymbolAddress((void**)&qhh, g_Qhh); cudaGetSymbolAddress((void**)&qhl, g_Qhl);
    cudaGetSymbolAddress((void**)&khh, g_Khh); cudaGetSymbolAddress((void**)&khl, g_Khl);
    cudaGetSymbolAddress((void**)&vhh, g_Vhh); cudaGetSymbolAddress((void**)&vhl, g_Vhl);
    cudaGetSymbolAddress((void**)&ohh, g_Ohh); cudaGetSymbolAddress((void**)&ohl, g_Ohl);

    static bool attr_done = false;
    if (!attr_done) {
        cudaFuncSetAttribute(tc_gemm_qkv_kernel,
                             cudaFuncAttributeMaxDynamicSharedMemorySize, GSMEM);
        cudaFuncSetAttribute(tc_gemm_kernel,
                             cudaFuncAttributeMaxDynamicSharedMemorySize, GSMEM);
        cudaFuncSetAttribute(flash_mma_kernel,
                             cudaFuncAttributeMaxDynamicSharedMemorySize, FSMEM);
        attr_done = true;
    }

    // [0] all splits in one launch
    split_all_kernel<<<dim3((SEQL * DMODEL / 4) / 256, 1, 7), 256>>>(
        Q, K, V, WQ, WK, WV, WO,
        qih, qil, kih, kil, vih, vil,
        wqh, wql, wkh, wkl, wvh, wvl, woh, wol);

    // [1] fused Q/K/V projection GEMMs: 384 CTAs in one launch
    tc_gemm_qkv_kernel<<<dim3(12, SEQL / 128), 512, GSMEM>>>(
        qih, qil, kih, kil, vih, vil,
        wqh, wql, wkh, wkl, wvh, wvl,
        qhh, qhl, khh, khl, vhh, vhl);

    // [2] flash attention: paired q-tiles (p, 31-p), uniform 33 iters/CTA
    flash_mma_kernel<<<dim3(16, NH), 256, FSMEM>>>(
        qhh, qhl, khh, khl, vhh, ohh, ohl);

    // [3] output projection: 2-term, fp32 out
    tc_gemm_kernel<<<dim3(DMODEL / 256, SEQL / 128), 512, GSMEM>>>(
        ohh, ohl, woh, wol, out, 2);
}